// round 8
// baseline (speedup 1.0000x reference)
#include <cuda_runtime.h>
#include <cuda_fp16.h>
#include <cstdint>

#define NEGV (-1e30f)

// ============================ scratch (no allocs) ============================
__device__ __half   g_Xh[33554432];                     // X fp16
__device__ __half   g_Yh[33554432];                     // Y fp16
__device__ __half   g_Kh[33554432];                     // K fp16 [b][t][h]
__device__ __half   g_Qh[33554432];                     // Q fp16 [b][t][h]
__device__ __half   g_Vth[33554432];                    // V^T fp16 [b][h][t]
__device__ __half   g_Wth[786432];                      // 3x W^T [h][d] fp16
__device__ uint8_t  g_dagU8[1048576];                   // dag^T as u8 [t][s]

// ============================ PTX helpers (base sm_103 ISA) ==================
__device__ __forceinline__ uint32_t smem_u32(const void* p) {
    uint32_t a;
    asm("{ .reg .u64 t; cvta.to.shared.u64 t, %1; cvt.u32.u64 %0, t; }" : "=r"(a) : "l"(p));
    return a;
}
#define CP_ASYNC16(dst, src) \
    asm volatile("cp.async.cg.shared.global [%0], [%1], 16;" :: "r"(dst), "l"(src))
#define CP_COMMIT() asm volatile("cp.async.commit_group;" ::: "memory")
#define CP_WAIT(n)  asm volatile("cp.async.wait_group %0;" :: "n"(n) : "memory")

__device__ __forceinline__ void cp_wait_n(int n) {
    switch (n) {
        case 0: CP_WAIT(0); break;
        case 1: CP_WAIT(1); break;
        default: CP_WAIT(2); break;
    }
}

__device__ __forceinline__ void ldsm_x4(uint32_t& r0, uint32_t& r1, uint32_t& r2, uint32_t& r3,
                                        uint32_t addr) {
    asm volatile("ldmatrix.sync.aligned.m8n8.x4.shared.b16 {%0,%1,%2,%3}, [%4];"
                 : "=r"(r0), "=r"(r1), "=r"(r2), "=r"(r3) : "r"(addr));
}
__device__ __forceinline__ void mma_f16(float* c, const uint32_t* a, uint32_t b0, uint32_t b1) {
    asm volatile(
        "mma.sync.aligned.m16n8k16.row.col.f32.f16.f16.f32 "
        "{%0,%1,%2,%3}, {%4,%5,%6,%7}, {%8,%9}, {%0,%1,%2,%3};"
        : "+f"(c[0]), "+f"(c[1]), "+f"(c[2]), "+f"(c[3])
        : "r"(a[0]), "r"(a[1]), "r"(a[2]), "r"(a[3]), "r"(b0), "r"(b1));
}
#define SWZ128(o) ((o) ^ (((o) >> 3) & 0x70))

// ============================ small utility kernels ==========================
__global__ __launch_bounds__(256) void half_kernel(const float4* __restrict__ src,
                                                   uint2* __restrict__ h) {
    int i = blockIdx.x * 256 + threadIdx.x;
    float4 v = src[i];
    uint2 hh;
    hh.x = (uint32_t)__half_as_ushort(__float2half_rn(v.x)) |
           ((uint32_t)__half_as_ushort(__float2half_rn(v.y)) << 16);
    hh.y = (uint32_t)__half_as_ushort(__float2half_rn(v.z)) |
           ((uint32_t)__half_as_ushort(__float2half_rn(v.w)) << 16);
    h[i] = hh;
}

__global__ __launch_bounds__(256) void wt_half_kernel(const float* __restrict__ W,
                                                      __half* __restrict__ th) {
    int i = blockIdx.x * 256 + threadIdx.x;           // Wt[h][d] = W[d][h]
    int hh = i >> 9, d = i & 511;
    th[i] = __float2half_rn(W[d * 512 + hh]);
}

__global__ __launch_bounds__(256) void dagu8_kernel(const float* __restrict__ dag,
                                                    uint8_t* __restrict__ dagU) {
    int i = blockIdx.x * 256 + threadIdx.x;           // dagU[t][s] = dag[s][t] != 0
    int t = i >> 10, s = i & 1023;
    dagU[i] = (dag[s * 1024 + t] != 0.0f) ? 1 : 0;
}

// ============================ HMMA fp16 GEMM (projections) ===================
// C[256x128 CTA] = A[M,K] x B[N,K]^T, fp32 accum. 8 warps 4(M)x2(N),
// warp tile 64x64, BK=64, 3-stage cp.async. EPI: 4 fp16(+bias) row-major;
// 3 fp16(+bias) transposed [h][t].
static constexpr int STAGE_BYTES = 49152;
static constexpr int SMEM_BYTES  = 3 * STAGE_BYTES;   // 144KB

template <int EPI>
__global__ __launch_bounds__(256, 1) void gemm_hmma(
    const __half* __restrict__ A, long long sA, int lda,
    const __half* __restrict__ B, long long sB, int ldb,
    int Kdim, __half* __restrict__ Ch, const float* __restrict__ bias)
{
    extern __shared__ char smem[];
    const int b = blockIdx.z;
    A += (long long)b * sA;
    B += (long long)b * sB;

    const int mBase = blockIdx.y * 256;
    const int nBase = blockIdx.x * 128;
    const int tid = threadIdx.x, wid = tid >> 5, lane = tid & 31;
    const int warpM = (wid >> 1) * 64;
    const int warpN = (wid & 1) * 64;

    const uint32_t sb = smem_u32(smem);
    const __half* srcA = A + (long long)mBase * lda;
    const __half* srcB = B + (long long)nBase * ldb;

    auto load_stage = [&](int st, int k0) {
        const uint32_t stBase = sb + st * STAGE_BYTES;
#pragma unroll
        for (int i = 0; i < 8; i++) {
            const int idx = (i << 8) | tid;
            const int row = idx >> 3, k8 = (idx & 7) << 3;
            CP_ASYNC16(stBase + SWZ128((uint32_t)(row * 128 + k8 * 2)),
                       srcA + (long long)row * lda + k0 + k8);
        }
#pragma unroll
        for (int i = 0; i < 4; i++) {
            const int idx = (i << 8) | tid;
            const int row = idx >> 3, k8 = (idx & 7) << 3;
            CP_ASYNC16(stBase + 32768 + SWZ128((uint32_t)(row * 128 + k8 * 2)),
                       srcB + (long long)row * ldb + k0 + k8);
        }
    };

    float acc[4][8][4];
#pragma unroll
    for (int mi = 0; mi < 4; mi++)
#pragma unroll
        for (int ni = 0; ni < 8; ni++)
#pragma unroll
            for (int c = 0; c < 4; c++) acc[mi][ni][c] = 0.0f;

    const int aRow  = warpM + (lane & 15);
    const int bRow  = warpN + (lane & 15);
    const int kHalf = (lane >> 4) * 8;

    const int nch = Kdim >> 6;
    load_stage(0, 0);
    CP_COMMIT();
    if (nch > 1) { load_stage(1, 64); CP_COMMIT(); }

    for (int i = 0; i < nch; i++) {
        const int st = i % 3;
        if (i + 2 < nch)      { load_stage((i + 2) % 3, (i + 2) << 6); CP_COMMIT(); CP_WAIT(2); }
        else if (i + 1 < nch) { CP_WAIT(1); }
        else                  { CP_WAIT(0); }
        __syncthreads();

        const uint32_t aB = sb + st * STAGE_BYTES;
        const uint32_t bB = aB + 32768;
#pragma unroll
        for (int ks = 0; ks < 4; ks++) {
            const int kb = (ks * 16 + kHalf) * 2;
            uint32_t bf[8][2];
#pragma unroll
            for (int np = 0; np < 4; np++) {
                const uint32_t offB = SWZ128((uint32_t)((bRow + np * 16) * 128 + kb));
                uint32_t r0, r1, r2, r3;
                ldsm_x4(r0, r1, r2, r3, bB + offB);
                bf[np * 2 + 0][0] = r0; bf[np * 2 + 0][1] = r2;
                bf[np * 2 + 1][0] = r1; bf[np * 2 + 1][1] = r3;
            }
            uint32_t af[4][4];
#pragma unroll
            for (int mi = 0; mi < 4; mi++) {
                const uint32_t offA = SWZ128((uint32_t)((aRow + mi * 16) * 128 + kb));
                ldsm_x4(af[mi][0], af[mi][1], af[mi][2], af[mi][3], aB + offA);
            }
#pragma unroll
            for (int mi = 0; mi < 4; mi++)
#pragma unroll
                for (int ni = 0; ni < 8; ni++)
                    mma_f16(acc[mi][ni], af[mi], bf[ni][0], bf[ni][1]);
        }
        __syncthreads();
    }

    uint32_t* stgU = (uint32_t*)smem;
    const int rBase = lane >> 2;
    const int cOff  = (lane & 3) * 2;

#pragma unroll
    for (int mi = 0; mi < 4; mi++) {
        const int r0 = warpM + mi * 16 + rBase;
        const int r1 = r0 + 8;
#pragma unroll
        for (int ni = 0; ni < 8; ni++) {
            const int col = warpN + ni * 8 + cOff;
            const float b0 = bias[nBase + col], b1 = bias[nBase + col + 1];
            if (EPI == 4) {
                stgU[r0 * 132 + col]     = (uint32_t)__half_as_ushort(__float2half_rn(acc[mi][ni][0] + b0));
                stgU[r0 * 132 + col + 1] = (uint32_t)__half_as_ushort(__float2half_rn(acc[mi][ni][1] + b1));
                stgU[r1 * 132 + col]     = (uint32_t)__half_as_ushort(__float2half_rn(acc[mi][ni][2] + b0));
                stgU[r1 * 132 + col + 1] = (uint32_t)__half_as_ushort(__float2half_rn(acc[mi][ni][3] + b1));
            } else {
                stgU[col * 260 + r0]       = (uint32_t)__half_as_ushort(__float2half_rn(acc[mi][ni][0] + b0));
                stgU[(col + 1) * 260 + r0] = (uint32_t)__half_as_ushort(__float2half_rn(acc[mi][ni][1] + b1));
                stgU[col * 260 + r1]       = (uint32_t)__half_as_ushort(__float2half_rn(acc[mi][ni][2] + b0));
                stgU[(col + 1) * 260 + r1] = (uint32_t)__half_as_ushort(__float2half_rn(acc[mi][ni][3] + b1));
            }
        }
    }
    __syncthreads();

    if (EPI == 4) {
#pragma unroll
        for (int i = 0; i < 32; i++) {
            const int q = tid + i * 256;
            const int row = q >> 5, c4 = (q & 31) << 2;
            uint32_t w0 = stgU[row * 132 + c4], w1 = stgU[row * 132 + c4 + 1];
            uint32_t w2 = stgU[row * 132 + c4 + 2], w3 = stgU[row * 132 + c4 + 3];
            uint2 hh;
            hh.x = (w0 & 0xFFFF) | (w1 << 16);  hh.y = (w2 & 0xFFFF) | (w3 << 16);
            const long long gi = (long long)(mBase + row) * 512 + nBase + c4;
            *(uint2*)(Ch + gi) = hh;
        }
    } else {
#pragma unroll
        for (int i = 0; i < 32; i++) {
            const int q = tid + i * 256;
            const int c = q >> 6, r4 = (q & 63) << 2;
            uint32_t w0 = stgU[c * 260 + r4], w1 = stgU[c * 260 + r4 + 1];
            uint32_t w2 = stgU[c * 260 + r4 + 2], w3 = stgU[c * 260 + r4 + 3];
            uint2 hh;
            hh.x = (w0 & 0xFFFF) | (w1 << 16);  hh.y = (w2 & 0xFFFF) | (w3 << 16);
            const int gt = mBase + r4;
            const int bat = gt >> 10, t0 = gt & 1023;
            const long long gi = ((long long)bat * 512 + (nBase + c)) * 1024 + t0;
            *(uint2*)(Ch + gi) = hh;
        }
    }
}

// ============================ fused flash attention ==========================
// Per CTA: one batch b, one 64-query tile. Loops 8 s-tiles of 128:
//   S = Q Kt^T (fp16 mma, fp32 acc) -> scale+dag mask -> online softmax ->
//   P fp16 in smem -> O += P @ V (V^T streamed, 80B-row padded layout).
// smem map (bytes):
//   0       Qs      65536   (8 chunks x 64rows x 128B, SW128)
//   65536   Ks      3x16384 (128rows x 128B, SW128)
//   114688  dag     8192    (64 x 128 u8, plain)
//   122880  Ps      16384   (2 chunks x 64rows x 128B, SW128)
//   139264  stats   4096    (m 64f | alpha 64f | l 64f | red 256f | psum 256f)
//   143360  Vs      2x40960 (512rows x 80B pad, plain; conflict-free ldsm)
static constexpr int FL_QS = 0;
static constexpr int FL_KS = 65536;
static constexpr int FL_DS = 114688;
static constexpr int FL_PS = 122880;
static constexpr int FL_ST = 139264;
static constexpr int FL_VS = 143360;
static constexpr int FL_SMEM = 225280;

__global__ __launch_bounds__(256, 1) void flash_kernel(
    const __half* __restrict__ Q, const __half* __restrict__ K,
    const __half* __restrict__ Vt, const uint8_t* __restrict__ dagU,
    float* __restrict__ O)
{
    extern __shared__ char smem[];
    const int b  = blockIdx.y;
    const int t0 = blockIdx.x * 64;
    const int tid = threadIdx.x, wid = tid >> 5, lane = tid & 31;
    const int warpM = (wid & 4) ? 32 : 0;    // S rows / O rows
    const int warpN = (wid & 3);             // S: 32-col group; O: 128-col group
    const uint32_t sb = smem_u32(smem);

    const __half* Qb = Q  + ((long long)b * 1024 + t0) * 512;
    const __half* Kb = K  + (long long)b * 1024 * 512;
    const __half* Vb = Vt + (long long)b * 512 * 1024;

    float* sm_m  = (float*)(smem + FL_ST);
    float* sm_a  = (float*)(smem + FL_ST + 256);
    float* sm_l  = (float*)(smem + FL_ST + 512);
    float* sm_rd = (float*)(smem + FL_ST + 768);    // [4][64]
    float* sm_ps = (float*)(smem + FL_ST + 1792);   // [4][64]
    uint8_t* dags = (uint8_t*)(smem + FL_DS);

    // ---- load Q (resident), init stats ----
#pragma unroll
    for (int i = 0; i < 16; i++) {
        const int idx = i * 256 + tid;
        const int kc = idx >> 9, w = idx & 511;
        const int row = w >> 3, h8 = (w & 7) << 3;
        CP_ASYNC16(sb + FL_QS + kc * 8192 + SWZ128((uint32_t)(row * 128 + h8 * 2)),
                   Qb + row * 512 + kc * 64 + h8);
    }
    CP_COMMIT();
    if (tid < 64) { sm_m[tid] = NEGV; sm_l[tid] = 0.0f; }
    __syncthreads();

    float acc_o[2][16][4];
#pragma unroll
    for (int mi = 0; mi < 2; mi++)
#pragma unroll
        for (int nn = 0; nn < 16; nn++)
#pragma unroll
            for (int c = 0; c < 4; c++) acc_o[mi][nn][c] = 0.0f;

    const int kHalf = (lane >> 4) * 8;
    const int aRow  = warpM + (lane & 15);

    for (int sT = 0; sT < 8; sT++) {
        const int s0 = sT * 128;

        auto loadK = [&](int buf, int hk0) {
#pragma unroll
            for (int i = 0; i < 4; i++) {
                const int idx = i * 256 + tid;
                const int row = idx >> 3, h8 = (idx & 7) << 3;
                CP_ASYNC16(sb + FL_KS + buf * 16384 + SWZ128((uint32_t)(row * 128 + h8 * 2)),
                           Kb + (long long)(s0 + row) * 512 + hk0 + h8);
            }
        };
        auto loadV = [&](int buf, int soff) {
#pragma unroll
            for (int i = 0; i < 8; i++) {
                const int idx = i * 256 + tid;
                const int row = idx >> 2, s8 = (idx & 3) << 3;
                CP_ASYNC16(sb + FL_VS + buf * 40960 + (uint32_t)(row * 80 + s8 * 2),
                           Vb + (long long)row * 1024 + s0 + soff + s8);
            }
        };

        // pre-issue: [K0 + dag] [K1]
        loadK(0, 0);
        {   // dag tile 64x128 u8
#pragma unroll
            for (int i = 0; i < 2; i++) {
                const int idx = i * 256 + tid;
                const int row = idx >> 3, s16 = (idx & 7) << 4;
                CP_ASYNC16(sb + FL_DS + (uint32_t)(row * 128 + s16),
                           dagU + (long long)(t0 + row) * 1024 + s0 + s16);
            }
        }
        CP_COMMIT();
        loadK(1, 64);
        CP_COMMIT();

        float acc_s[2][4][4];
#pragma unroll
        for (int mi = 0; mi < 2; mi++)
#pragma unroll
            for (int ni = 0; ni < 4; ni++)
#pragma unroll
                for (int c = 0; c < 4; c++) acc_s[mi][ni][c] = 0.0f;

        // ---- S GEMM: 8 h-chunks of 64 ----
        for (int i = 0; i < 8; i++) {
            // waits: i<3 -> 1 ; 3..6 -> 2 ; 7 -> 0
            cp_wait_n((i < 3) ? 1 : ((i < 7) ? 2 : 0));
            __syncthreads();
            if (i < 6)  { loadK((i + 2) % 3, (i + 2) * 64); CP_COMMIT(); }
            if (i == 2) { loadV(0, 0);  CP_COMMIT(); }
            if (i == 4) { loadV(1, 32); CP_COMMIT(); }

            const uint32_t qB = sb + FL_QS + i * 8192;
            const uint32_t kB = sb + FL_KS + (i % 3) * 16384;
#pragma unroll
            for (int ks = 0; ks < 4; ks++) {
                const int kb = (ks * 16 + kHalf) * 2;
                uint32_t af[2][4], bf[4][2];
#pragma unroll
                for (int mi = 0; mi < 2; mi++)
                    ldsm_x4(af[mi][0], af[mi][1], af[mi][2], af[mi][3],
                            qB + SWZ128((uint32_t)((aRow + mi * 16) * 128 + kb)));
#pragma unroll
                for (int np = 0; np < 2; np++) {
                    uint32_t r0, r1, r2, r3;
                    ldsm_x4(r0, r1, r2, r3,
                            kB + SWZ128((uint32_t)((warpN * 32 + np * 16 + (lane & 15)) * 128 + kb)));
                    bf[np * 2 + 0][0] = r0; bf[np * 2 + 0][1] = r2;
                    bf[np * 2 + 1][0] = r1; bf[np * 2 + 1][1] = r3;
                }
#pragma unroll
                for (int mi = 0; mi < 2; mi++)
#pragma unroll
                    for (int ni = 0; ni < 4; ni++)
                        mma_f16(acc_s[mi][ni], af[mi], bf[ni][0], bf[ni][1]);
            }
            __syncthreads();
        }

        // ---- softmax phase ----
        const float scale = 0.044194173824159216f;
        float rmx[2][2] = {{-3.4e38f, -3.4e38f}, {-3.4e38f, -3.4e38f}};
#pragma unroll
        for (int mi = 0; mi < 2; mi++)
#pragma unroll
            for (int ni = 0; ni < 4; ni++)
#pragma unroll
                for (int c = 0; c < 4; c++) {
                    const int rh = c >> 1;
                    const int row = warpM + mi * 16 + (lane >> 2) + rh * 8;
                    const int col = warpN * 32 + ni * 8 + (lane & 3) * 2 + (c & 1);
                    float v = acc_s[mi][ni][c] * scale;
                    bool ok = (dags[row * 128 + col] != 0) && (v != 0.0f);
                    float lg = ok ? v : NEGV;
                    acc_s[mi][ni][c] = lg;
                    rmx[mi][rh] = fmaxf(rmx[mi][rh], lg);
                }
#pragma unroll
        for (int mi = 0; mi < 2; mi++)
#pragma unroll
            for (int rh = 0; rh < 2; rh++) {
                float v = rmx[mi][rh];
                v = fmaxf(v, __shfl_xor_sync(0xffffffffu, v, 1));
                v = fmaxf(v, __shfl_xor_sync(0xffffffffu, v, 2));
                if ((lane & 3) == 0)
                    sm_rd[warpN * 64 + warpM + mi * 16 + (lane >> 2) + rh * 8] = v;
            }
        __syncthreads();
        if (tid < 64) {
            float tm = fmaxf(fmaxf(sm_rd[tid], sm_rd[64 + tid]),
                             fmaxf(sm_rd[128 + tid], sm_rd[192 + tid]));
            float mo = sm_m[tid], mn = fmaxf(mo, tm);
            sm_m[tid] = mn;
            sm_a[tid] = __expf(mo - mn);
        }
        __syncthreads();

        float mnv[2][2], alv[2][2], rsm[2][2] = {{0.f, 0.f}, {0.f, 0.f}};
#pragma unroll
        for (int mi = 0; mi < 2; mi++)
#pragma unroll
            for (int rh = 0; rh < 2; rh++) {
                const int row = warpM + mi * 16 + (lane >> 2) + rh * 8;
                mnv[mi][rh] = sm_m[row];
                alv[mi][rh] = sm_a[row];
            }
#pragma unroll
        for (int mi = 0; mi < 2; mi++)
#pragma unroll
            for (int ni = 0; ni < 4; ni++)
#pragma unroll
                for (int rh = 0; rh < 2; rh++) {
                    float lg0 = acc_s[mi][ni][rh * 2], lg1 = acc_s[mi][ni][rh * 2 + 1];
                    float p0 = (lg0 == NEGV) ? 0.0f : __expf(lg0 - mnv[mi][rh]);
                    float p1 = (lg1 == NEGV) ? 0.0f : __expf(lg1 - mnv[mi][rh]);
                    rsm[mi][rh] += p0 + p1;
                    const int row = warpM + mi * 16 + (lane >> 2) + rh * 8;
                    const int col0 = warpN * 32 + ni * 8 + (lane & 3) * 2;
                    const int kc = col0 >> 6;
                    uint32_t pk = (uint32_t)__half_as_ushort(__float2half_rn(p0)) |
                                  ((uint32_t)__half_as_ushort(__float2half_rn(p1)) << 16);
                    *(uint32_t*)(smem + FL_PS + kc * 8192 +
                                 SWZ128((uint32_t)(row * 128 + (col0 & 63) * 2))) = pk;
                }
#pragma unroll
        for (int mi = 0; mi < 2; mi++)
#pragma unroll
            for (int rh = 0; rh < 2; rh++) {
                float v = rsm[mi][rh];
                v += __shfl_xor_sync(0xffffffffu, v, 1);
                v += __shfl_xor_sync(0xffffffffu, v, 2);
                if ((lane & 3) == 0)
                    sm_ps[warpN * 64 + warpM + mi * 16 + (lane >> 2) + rh * 8] = v;
            }
        // scale O by alpha
#pragma unroll
        for (int mi = 0; mi < 2; mi++)
#pragma unroll
            for (int nn = 0; nn < 16; nn++)
#pragma unroll
                for (int c = 0; c < 4; c++)
                    acc_o[mi][nn][c] *= alv[mi][c >> 1];
        __syncthreads();
        if (tid < 64)
            sm_l[tid] = sm_l[tid] * sm_a[tid] +
                        (sm_ps[tid] + sm_ps[64 + tid] + sm_ps[128 + tid] + sm_ps[192 + tid]);

        // ---- O GEMM: 4 s-quarters of 32 ----
        for (int j = 0; j < 4; j++) {
            if (j >= 2) CP_WAIT(0);
            if (j >= 1) __syncthreads();
            if (j == 1) { loadV(0, 64); CP_COMMIT(); }
            if (j == 2) { loadV(1, 96); CP_COMMIT(); }

            const uint32_t vB = sb + FL_VS + (j & 1) * 40960;
#pragma unroll
            for (int ksl = 0; ksl < 2; ksl++) {
                const int s16 = j * 32 + ksl * 16;
                const int kc = s16 >> 6, scl = s16 & 63;
                uint32_t af[2][4], bf[16][2];
#pragma unroll
                for (int mi = 0; mi < 2; mi++)
                    ldsm_x4(af[mi][0], af[mi][1], af[mi][2], af[mi][3],
                            sb + FL_PS + kc * 8192 +
                            SWZ128((uint32_t)((aRow + mi * 16) * 128 + (scl + kHalf) * 2)));
#pragma unroll
                for (int np = 0; np < 8; np++) {
                    uint32_t r0, r1, r2, r3;
                    ldsm_x4(r0, r1, r2, r3,
                            vB + (uint32_t)((warpN * 128 + np * 16 + (lane & 15)) * 80 +
                                            (ksl * 16 + kHalf) * 2));
                    bf[np * 2 + 0][0] = r0; bf[np * 2 + 0][1] = r2;
                    bf[np * 2 + 1][0] = r1; bf[np * 2 + 1][1] = r3;
                }
#pragma unroll
                for (int mi = 0; mi < 2; mi++)
#pragma unroll
                    for (int nn = 0; nn < 16; nn++)
                        mma_f16(acc_o[mi][nn], af[mi], bf[nn][0], bf[nn][1]);
            }
        }
        __syncthreads();
    }

    // ---- epilogue: normalize by l, stage, coalesced write ----
    float inv[2][2];
#pragma unroll
    for (int mi = 0; mi < 2; mi++)
#pragma unroll
        for (int rh = 0; rh < 2; rh++) {
            const int row = warpM + mi * 16 + (lane >> 2) + rh * 8;
            float lv = sm_l[row];
            inv[mi][rh] = (lv > 0.0f) ? (1.0f / lv) : 0.0f;
        }
    __syncthreads();

    float* stg = (float*)smem;                 // 64 rows x stride 524 floats
#pragma unroll
    for (int mi = 0; mi < 2; mi++)
#pragma unroll
        for (int nn = 0; nn < 16; nn++)
#pragma unroll
            for (int rh = 0; rh < 2; rh++) {
                const int row = warpM + mi * 16 + (lane >> 2) + rh * 8;
                const int col = warpN * 128 + nn * 8 + (lane & 3) * 2;
                float2 o;
                o.x = acc_o[mi][nn][rh * 2]     * inv[mi][rh];
                o.y = acc_o[mi][nn][rh * 2 + 1] * inv[mi][rh];
                *(float2*)(stg + row * 524 + col) = o;
            }
    __syncthreads();

    float* Og = O + ((long long)b * 1024 + t0) * 512;
#pragma unroll
    for (int it = 0; it < 32; it++) {
        const int idx = it * 256 + tid;
        const int row = idx >> 7, c4 = (idx & 127) << 2;
        float4 v = *(float4*)(stg + row * 524 + c4);
        *(float4*)(Og + (long long)row * 512 + c4) = v;
    }
}

// ============================ launch =========================================
extern "C" void kernel_launch(void* const* d_in, const int* in_sizes, int n_in,
                              void* d_out, int out_size)
{
    const float* X   = (const float*)d_in[0];
    const float* Y   = (const float*)d_in[1];
    const float* dag = (const float*)d_in[2];
    const float* Wk  = (const float*)d_in[3];
    const float* bk  = (const float*)d_in[4];
    const float* Wq  = (const float*)d_in[5];
    const float* bq  = (const float*)d_in[6];
    const float* Wv  = (const float*)d_in[7];
    const float* bv  = (const float*)d_in[8];
    float* O = (float*)d_out;

    __half *Xh, *Yh, *Kh, *Qh, *Vth, *Wth;
    uint8_t* dagU;
    cudaGetSymbolAddress((void**)&Xh, g_Xh);
    cudaGetSymbolAddress((void**)&Yh, g_Yh);
    cudaGetSymbolAddress((void**)&Kh, g_Kh);
    cudaGetSymbolAddress((void**)&Qh, g_Qh);
    cudaGetSymbolAddress((void**)&Vth, g_Vth);
    cudaGetSymbolAddress((void**)&Wth, g_Wth);
    cudaGetSymbolAddress((void**)&dagU, g_dagU8);

    cudaFuncSetAttribute(gemm_hmma<4>, cudaFuncAttributeMaxDynamicSharedMemorySize, SMEM_BYTES);
    cudaFuncSetAttribute(gemm_hmma<3>, cudaFuncAttributeMaxDynamicSharedMemorySize, SMEM_BYTES);
    cudaFuncSetAttribute(flash_kernel, cudaFuncAttributeMaxDynamicSharedMemorySize, FL_SMEM);

    // ---- prep ----
    half_kernel<<<32768, 256>>>((const float4*)X, (uint2*)Xh);
    half_kernel<<<32768, 256>>>((const float4*)Y, (uint2*)Yh);
    wt_half_kernel<<<1024, 256>>>(Wk, Wth);
    wt_half_kernel<<<1024, 256>>>(Wq, Wth + 262144);
    wt_half_kernel<<<1024, 256>>>(Wv, Wth + 524288);
    dagu8_kernel<<<4096, 256>>>(dag, dagU);

    dim3 blk(256);

    // ---- projections: [65536,512] x Wt[512,512]^T ----
    dim3 gproj(4, 256, 1);
    gemm_hmma<4><<<gproj, blk, SMEM_BYTES>>>(Xh, 0, 512, Wth,          0, 512, 512, Kh, bk);
    gemm_hmma<4><<<gproj, blk, SMEM_BYTES>>>(Yh, 0, 512, Wth + 262144, 0, 512, 512, Qh, bq);
    gemm_hmma<3><<<gproj, blk, SMEM_BYTES>>>(Xh, 0, 512, Wth + 524288, 0, 512, 512, Vth, bv);

    // ---- fused attention: scores + mask + softmax + A@V ----
    dim3 gfl(16, 64, 1);
    flash_kernel<<<gfl, blk, FL_SMEM>>>(Qh, Kh, Vth, dagU, O);
}

// round 9
// speedup vs baseline: 1.0765x; 1.0765x over previous
#include <cuda_runtime.h>
#include <cuda_fp16.h>
#include <cstdint>

#define NEGV (-1e30f)

// ============================ scratch (no allocs) ============================
__device__ __half   g_Xh[33554432];                     // X fp16
__device__ __half   g_Yh[33554432];                     // Y fp16
__device__ __half   g_Kh[33554432];                     // K fp16 [b][t][h]
__device__ __half   g_Qh[33554432];                     // Q fp16 [b][t][h]
__device__ __half   g_Vth[33554432];                    // V^T fp16 [b][h][t]
__device__ float    g_S [67108864];                     // logits [b][t][s]
__device__ __half   g_Ph[67108864];                     // probs fp16
__device__ __half   g_Wth[786432];                      // 3x W^T [h][d] fp16
__device__ uint8_t  g_dagU8[1048576];                   // dag^T as u8 [t][s]

// ============================ PTX helpers (base sm_103 ISA) ==================
__device__ __forceinline__ uint32_t smem_u32(const void* p) {
    uint32_t a;
    asm("{ .reg .u64 t; cvta.to.shared.u64 t, %1; cvt.u32.u64 %0, t; }" : "=r"(a) : "l"(p));
    return a;
}
#define CP_ASYNC16(dst, src) \
    asm volatile("cp.async.cg.shared.global [%0], [%1], 16;" :: "r"(dst), "l"(src))
#define CP_COMMIT() asm volatile("cp.async.commit_group;" ::: "memory")
#define CP_WAIT(n)  asm volatile("cp.async.wait_group %0;" :: "n"(n) : "memory")

__device__ __forceinline__ void ldsm_x4(uint32_t& r0, uint32_t& r1, uint32_t& r2, uint32_t& r3,
                                        uint32_t addr) {
    asm volatile("ldmatrix.sync.aligned.m8n8.x4.shared.b16 {%0,%1,%2,%3}, [%4];"
                 : "=r"(r0), "=r"(r1), "=r"(r2), "=r"(r3) : "r"(addr));
}
__device__ __forceinline__ void mma_f16(float* c, const uint32_t* a, uint32_t b0, uint32_t b1) {
    asm volatile(
        "mma.sync.aligned.m16n8k16.row.col.f32.f16.f16.f32 "
        "{%0,%1,%2,%3}, {%4,%5,%6,%7}, {%8,%9}, {%0,%1,%2,%3};"
        : "+f"(c[0]), "+f"(c[1]), "+f"(c[2]), "+f"(c[3])
        : "r"(a[0]), "r"(a[1]), "r"(a[2]), "r"(a[3]), "r"(b0), "r"(b1));
}
#define SWZ128(o) ((o) ^ (((o) >> 3) & 0x70))

// ============================ small utility kernels ==========================
__global__ __launch_bounds__(256) void half_kernel(const float4* __restrict__ src,
                                                   uint2* __restrict__ h) {
    int i = blockIdx.x * 256 + threadIdx.x;
    float4 v = src[i];
    uint2 hh;
    hh.x = (uint32_t)__half_as_ushort(__float2half_rn(v.x)) |
           ((uint32_t)__half_as_ushort(__float2half_rn(v.y)) << 16);
    hh.y = (uint32_t)__half_as_ushort(__float2half_rn(v.z)) |
           ((uint32_t)__half_as_ushort(__float2half_rn(v.w)) << 16);
    h[i] = hh;
}

__global__ __launch_bounds__(256) void wt_half_kernel(const float* __restrict__ W,
                                                      __half* __restrict__ th) {
    int i = blockIdx.x * 256 + threadIdx.x;           // Wt[h][d] = W[d][h]
    int hh = i >> 9, d = i & 511;
    th[i] = __float2half_rn(W[d * 512 + hh]);
}

__global__ __launch_bounds__(256) void dagu8_kernel(const float* __restrict__ dag,
                                                    uint8_t* __restrict__ dagU) {
    int i = blockIdx.x * 256 + threadIdx.x;           // dagU[t][s] = dag[s][t] != 0
    int t = i >> 10, s = i & 1023;
    dagU[i] = (dag[s * 1024 + t] != 0.0f) ? 1 : 0;
}

// Row softmax over 1024 fp32 logits -> fp16 probs. 256 thr, shuffle reductions.
__global__ __launch_bounds__(256) void softmax_kernel(const float* __restrict__ S,
                                                      uint2* __restrict__ Ph) {
    const long long row = blockIdx.x;
    const float* p = S + row * 1024;
    const int tid = threadIdx.x, wid = tid >> 5, lane = tid & 31;
    float4 v = ((const float4*)p)[tid];

    __shared__ float sm[16];
    float m = fmaxf(fmaxf(v.x, v.y), fmaxf(v.z, v.w));
#pragma unroll
    for (int o = 16; o; o >>= 1) m = fmaxf(m, __shfl_xor_sync(0xffffffffu, m, o));
    if (lane == 0) sm[wid] = m;
    __syncthreads();
    float mx = fmaxf(fmaxf(fmaxf(sm[0], sm[1]), fmaxf(sm[2], sm[3])),
                     fmaxf(fmaxf(sm[4], sm[5]), fmaxf(sm[6], sm[7])));

    float4 e;
    e.x = __expf(v.x - mx); e.y = __expf(v.y - mx); e.z = __expf(v.z - mx); e.w = __expf(v.w - mx);
    float s = e.x + e.y + e.z + e.w;
#pragma unroll
    for (int o = 16; o; o >>= 1) s += __shfl_xor_sync(0xffffffffu, s, o);
    if (lane == 0) sm[8 + wid] = s;
    __syncthreads();
    float tot = (sm[8] + sm[9]) + (sm[10] + sm[11]) + (sm[12] + sm[13]) + (sm[14] + sm[15]);
    const float inv = 1.0f / tot;

    if (mx < -1e29f) { e.x = e.y = e.z = e.w = 0.0f; }
    else { e.x *= inv; e.y *= inv; e.z *= inv; e.w *= inv; }

    uint2 hh;
    hh.x = (uint32_t)__half_as_ushort(__float2half_rn(e.x)) |
           ((uint32_t)__half_as_ushort(__float2half_rn(e.y)) << 16);
    hh.y = (uint32_t)__half_as_ushort(__float2half_rn(e.z)) |
           ((uint32_t)__half_as_ushort(__float2half_rn(e.w)) << 16);
    Ph[row * 256 + tid] = hh;
}

// ============================ HMMA fp16 GEMM (1-pass) ========================
// C[256x128 CTA] = A[M,K] x B[N,K]^T, fp32 accum. 8 warps 4(M)x2(N),
// warp tile 64x64, BK=64, 3-stage cp.async, ONE barrier per k-iter.
// EPI: 4 fp16(+bias) row-major (staged);  3 fp16(+bias) transposed (staged);
//      1 fp32 masked logits via u8 dag (DIRECT stores);  2 fp32 out (DIRECT).
static constexpr int STAGE_BYTES = 49152;
static constexpr int SMEM_BYTES  = 3 * STAGE_BYTES;   // 144KB

template <int EPI>
__global__ __launch_bounds__(256, 1) void gemm_hmma(
    const __half* __restrict__ A, long long sA, int lda,
    const __half* __restrict__ B, long long sB, int ldb,
    int Kdim,
    float* __restrict__ Cf, long long sCf,
    __half* __restrict__ Ch,
    const float* __restrict__ bias, const uint8_t* __restrict__ dagU)
{
    extern __shared__ char smem[];
    const int b = blockIdx.z;
    A += (long long)b * sA;
    B += (long long)b * sB;

    const int mBase = blockIdx.y * 256;
    const int nBase = blockIdx.x * 128;
    const int tid = threadIdx.x, wid = tid >> 5, lane = tid & 31;
    const int warpM = (wid >> 1) * 64;
    const int warpN = (wid & 1) * 64;

    const uint32_t sb = smem_u32(smem);
    const __half* srcA = A + (long long)mBase * lda;
    const __half* srcB = B + (long long)nBase * ldb;

    auto load_stage = [&](int st, int k0) {
        const uint32_t stBase = sb + st * STAGE_BYTES;
#pragma unroll
        for (int i = 0; i < 8; i++) {              // A: 256 rows x 8 chunks of 8
            const int idx = (i << 8) | tid;
            const int row = idx >> 3, k8 = (idx & 7) << 3;
            CP_ASYNC16(stBase + SWZ128((uint32_t)(row * 128 + k8 * 2)),
                       srcA + (long long)row * lda + k0 + k8);
        }
#pragma unroll
        for (int i = 0; i < 4; i++) {              // B: 128 rows x 8 chunks
            const int idx = (i << 8) | tid;
            const int row = idx >> 3, k8 = (idx & 7) << 3;
            CP_ASYNC16(stBase + 32768 + SWZ128((uint32_t)(row * 128 + k8 * 2)),
                       srcB + (long long)row * ldb + k0 + k8);
        }
    };

    float acc[4][8][4];
#pragma unroll
    for (int mi = 0; mi < 4; mi++)
#pragma unroll
        for (int ni = 0; ni < 8; ni++)
#pragma unroll
            for (int c = 0; c < 4; c++) acc[mi][ni][c] = 0.0f;

    const int aRow  = warpM + (lane & 15);
    const int bRow  = warpN + (lane & 15);
    const int kHalf = (lane >> 4) * 8;

    const int nch = Kdim >> 6;
    load_stage(0, 0);
    CP_COMMIT();
    if (nch > 1) { load_stage(1, 64); CP_COMMIT(); }

    for (int i = 0; i < nch; i++) {
        const int st = i % 3;
        // wait for stage i (it is the oldest pending group besides i+1)
        if (i + 1 < nch) CP_WAIT(1); else CP_WAIT(0);
        __syncthreads();                            // single barrier per iter
        if (i + 2 < nch) { load_stage((i + 2) % 3, (i + 2) << 6); CP_COMMIT(); }

        const uint32_t aB = sb + st * STAGE_BYTES;
        const uint32_t bB = aB + 32768;
#pragma unroll
        for (int ks = 0; ks < 4; ks++) {
            const int kb = (ks * 16 + kHalf) * 2;
            uint32_t bf[8][2];
#pragma unroll
            for (int np = 0; np < 4; np++) {
                const uint32_t offB = SWZ128((uint32_t)((bRow + np * 16) * 128 + kb));
                uint32_t r0, r1, r2, r3;
                ldsm_x4(r0, r1, r2, r3, bB + offB);
                bf[np * 2 + 0][0] = r0; bf[np * 2 + 0][1] = r2;
                bf[np * 2 + 1][0] = r1; bf[np * 2 + 1][1] = r3;
            }
            uint32_t af[4][4];
#pragma unroll
            for (int mi = 0; mi < 4; mi++) {
                const uint32_t offA = SWZ128((uint32_t)((aRow + mi * 16) * 128 + kb));
                ldsm_x4(af[mi][0], af[mi][1], af[mi][2], af[mi][3], aB + offA);
            }
#pragma unroll
            for (int mi = 0; mi < 4; mi++)
#pragma unroll
                for (int ni = 0; ni < 8; ni++)
                    mma_f16(acc[mi][ni], af[mi], bf[ni][0], bf[ni][1]);
        }
    }

    const int rBase = lane >> 2;
    const int cOff  = (lane & 3) * 2;

    if (EPI == 1) {
        // -------- scores: DIRECT float2 stores, scale + u8 dag mask ----------
        const float scale = 0.044194173824159216f;   // 1/sqrt(512)
#pragma unroll
        for (int mi = 0; mi < 4; mi++)
#pragma unroll
            for (int ni = 0; ni < 8; ni++)
#pragma unroll
                for (int rh = 0; rh < 2; rh++) {
                    const int t = mBase + warpM + mi * 16 + rBase + rh * 8;
                    const int s = nBase + warpN + ni * 8 + cOff;
                    const uint16_t dg = *(const uint16_t*)(dagU + (long long)t * 1024 + s);
                    float v0 = acc[mi][ni][rh * 2]     * scale;
                    float v1 = acc[mi][ni][rh * 2 + 1] * scale;
                    float2 o;
                    o.x = ((dg & 0xFF) && v0 != 0.0f) ? v0 : NEGV;
                    o.y = ((dg >> 8)  && v1 != 0.0f) ? v1 : NEGV;
                    *(float2*)(Cf + (long long)b * sCf + (long long)t * 1024 + s) = o;
                }
        return;
    }
    if (EPI == 2) {
        // -------- fp32 out: DIRECT float2 stores, ldc = 512 -------------------
#pragma unroll
        for (int mi = 0; mi < 4; mi++)
#pragma unroll
            for (int ni = 0; ni < 8; ni++)
#pragma unroll
                for (int rh = 0; rh < 2; rh++) {
                    const int row = mBase + warpM + mi * 16 + rBase + rh * 8;
                    const int col = nBase + warpN + ni * 8 + cOff;
                    float2 o;
                    o.x = acc[mi][ni][rh * 2];
                    o.y = acc[mi][ni][rh * 2 + 1];
                    *(float2*)(Cf + (long long)b * sCf + (long long)row * 512 + col) = o;
                }
        return;
    }

    // -------- fp16 epilogues: staged through smem for 16B-coalesced stores ----
    __syncthreads();   // all warps done reading stages before overwrite
    uint32_t* stgU = (uint32_t*)smem;

#pragma unroll
    for (int mi = 0; mi < 4; mi++) {
        const int r0 = warpM + mi * 16 + rBase;
        const int r1 = r0 + 8;
#pragma unroll
        for (int ni = 0; ni < 8; ni++) {
            const int col = warpN + ni * 8 + cOff;
            const float b0 = bias[nBase + col], b1 = bias[nBase + col + 1];
            if (EPI == 4) {
                stgU[r0 * 132 + col]     = (uint32_t)__half_as_ushort(__float2half_rn(acc[mi][ni][0] + b0));
                stgU[r0 * 132 + col + 1] = (uint32_t)__half_as_ushort(__float2half_rn(acc[mi][ni][1] + b1));
                stgU[r1 * 132 + col]     = (uint32_t)__half_as_ushort(__float2half_rn(acc[mi][ni][2] + b0));
                stgU[r1 * 132 + col + 1] = (uint32_t)__half_as_ushort(__float2half_rn(acc[mi][ni][3] + b1));
            } else {
                stgU[col * 260 + r0]       = (uint32_t)__half_as_ushort(__float2half_rn(acc[mi][ni][0] + b0));
                stgU[(col + 1) * 260 + r0] = (uint32_t)__half_as_ushort(__float2half_rn(acc[mi][ni][1] + b1));
                stgU[col * 260 + r1]       = (uint32_t)__half_as_ushort(__float2half_rn(acc[mi][ni][2] + b0));
                stgU[(col + 1) * 260 + r1] = (uint32_t)__half_as_ushort(__float2half_rn(acc[mi][ni][3] + b1));
            }
        }
    }
    __syncthreads();

    if (EPI == 4) {
#pragma unroll
        for (int i = 0; i < 32; i++) {
            const int q = tid + i * 256;
            const int row = q >> 5, c4 = (q & 31) << 2;
            uint32_t w0 = stgU[row * 132 + c4], w1 = stgU[row * 132 + c4 + 1];
            uint32_t w2 = stgU[row * 132 + c4 + 2], w3 = stgU[row * 132 + c4 + 3];
            uint2 hh;
            hh.x = (w0 & 0xFFFF) | (w1 << 16);  hh.y = (w2 & 0xFFFF) | (w3 << 16);
            const long long gi = (long long)(mBase + row) * 512 + nBase + c4;
            *(uint2*)(Ch + gi) = hh;
        }
    } else {
#pragma unroll
        for (int i = 0; i < 32; i++) {
            const int q = tid + i * 256;
            const int c = q >> 6, r4 = (q & 63) << 2;
            uint32_t w0 = stgU[c * 260 + r4], w1 = stgU[c * 260 + r4 + 1];
            uint32_t w2 = stgU[c * 260 + r4 + 2], w3 = stgU[c * 260 + r4 + 3];
            uint2 hh;
            hh.x = (w0 & 0xFFFF) | (w1 << 16);  hh.y = (w2 & 0xFFFF) | (w3 << 16);
            const int gt = mBase + r4;
            const int bat = gt >> 10, t0 = gt & 1023;
            const long long gi = ((long long)bat * 512 + (nBase + c)) * 1024 + t0;
            *(uint2*)(Ch + gi) = hh;
        }
    }
}

// ============================ launch =========================================
extern "C" void kernel_launch(void* const* d_in, const int* in_sizes, int n_in,
                              void* d_out, int out_size)
{
    const float* X   = (const float*)d_in[0];
    const float* Y   = (const float*)d_in[1];
    const float* dag = (const float*)d_in[2];
    const float* Wk  = (const float*)d_in[3];
    const float* bk  = (const float*)d_in[4];
    const float* Wq  = (const float*)d_in[5];
    const float* bq  = (const float*)d_in[6];
    const float* Wv  = (const float*)d_in[7];
    const float* bv  = (const float*)d_in[8];
    float* O = (float*)d_out;

    __half *Xh, *Yh, *Kh, *Qh, *Vth, *Wth, *Ph;
    float *S;
    uint8_t* dagU;
    cudaGetSymbolAddress((void**)&Xh, g_Xh);
    cudaGetSymbolAddress((void**)&Yh, g_Yh);
    cudaGetSymbolAddress((void**)&Kh, g_Kh);
    cudaGetSymbolAddress((void**)&Qh, g_Qh);
    cudaGetSymbolAddress((void**)&Vth, g_Vth);
    cudaGetSymbolAddress((void**)&Wth, g_Wth);
    cudaGetSymbolAddress((void**)&Ph, g_Ph);
    cudaGetSymbolAddress((void**)&S, g_S);
    cudaGetSymbolAddress((void**)&dagU, g_dagU8);

    cudaFuncSetAttribute(gemm_hmma<4>, cudaFuncAttributeMaxDynamicSharedMemorySize, SMEM_BYTES);
    cudaFuncSetAttribute(gemm_hmma<3>, cudaFuncAttributeMaxDynamicSharedMemorySize, SMEM_BYTES);
    cudaFuncSetAttribute(gemm_hmma<1>, cudaFuncAttributeMaxDynamicSharedMemorySize, SMEM_BYTES);
    cudaFuncSetAttribute(gemm_hmma<2>, cudaFuncAttributeMaxDynamicSharedMemorySize, SMEM_BYTES);

    // ---- prep ----
    half_kernel<<<32768, 256>>>((const float4*)X, (uint2*)Xh);
    half_kernel<<<32768, 256>>>((const float4*)Y, (uint2*)Yh);
    wt_half_kernel<<<1024, 256>>>(Wk, Wth);
    wt_half_kernel<<<1024, 256>>>(Wq, Wth + 262144);
    wt_half_kernel<<<1024, 256>>>(Wv, Wth + 524288);
    dagu8_kernel<<<4096, 256>>>(dag, dagU);

    dim3 blk(256);

    // ---- projections: [65536,512] x Wt[512,512]^T ----
    dim3 gproj(4, 256, 1);
    gemm_hmma<4><<<gproj, blk, SMEM_BYTES>>>(Xh, 0, 512, Wth,          0, 512, 512,
                                             nullptr, 0, Kh, bk, nullptr);
    gemm_hmma<4><<<gproj, blk, SMEM_BYTES>>>(Yh, 0, 512, Wth + 262144, 0, 512, 512,
                                             nullptr, 0, Qh, bq, nullptr);
    gemm_hmma<3><<<gproj, blk, SMEM_BYTES>>>(Xh, 0, 512, Wth + 524288, 0, 512, 512,
                                             nullptr, 0, Vth, bv, nullptr);

    // ---- scores: per-batch Q[1024,512] x K[1024,512]^T -> masked fp32 logits -
    dim3 gsc(8, 4, 64);
    gemm_hmma<1><<<gsc, blk, SMEM_BYTES>>>(Qh, 524288, 512, Kh, 524288, 512, 512,
                                           S, 1048576, nullptr, nullptr, dagU);

    // ---- softmax -> probs fp16 ----
    softmax_kernel<<<65536, 256>>>(S, (uint2*)Ph);

    // ---- output: per-batch P[1024,1024] x Vt[512,1024]^T -> fp32 out --------
    dim3 gav(4, 4, 64);
    gemm_hmma<2><<<gav, blk, SMEM_BYTES>>>(Ph, 1048576, 1024, Vth, 524288, 1024, 1024,
                                           O, 524288, nullptr, nullptr, nullptr);
}